// round 4
// baseline (speedup 1.0000x reference)
#include <cuda_runtime.h>
#include <cuda_bf16.h>
#include <math.h>
#include <cstdint>

#define NN 40000
#define EE 1280000
#define ETOT (EE + NN)
#define DD 256
#define BB 64
#define NCLS 20
#define KBIG 5000
#define KPBIG 5024   /* 157 * 32 */

// ---------------- scratch (static device allocations) ----------------------
__device__ float g_x0[NN * DD];
__device__ float g_x1[NN * DD];
__device__ float g_h[NN * DD];
__device__ float g_ssrc[NN * 8];
__device__ float g_sdst[NN * 8];
__device__ int   g_deg[NN];
__device__ int   g_off[NN + 1];
__device__ int   g_pos[NN];
__device__ int   g_csr[ETOT];
__device__ float g_p2[BB * DD];
__device__ float g_p0[BB * DD];
__device__ float g_cnt[BB];
__device__ __nv_bfloat16 g_wbt_hi[256 * KPBIG];
__device__ __nv_bfloat16 g_wbt_lo[256 * KPBIG];
__device__ __nv_bfloat16 g_w1t_hi[256 * 256];
__device__ __nv_bfloat16 g_w1t_lo[256 * 256];
__device__ __nv_bfloat16 g_w2t_hi[256 * 256];
__device__ __nv_bfloat16 g_w2t_lo[256 * 256];

__device__ __forceinline__ uint32_t smem_to_u32(const void* p) {
    uint32_t a;
    asm("{ .reg .u64 t; cvta.to.shared.u64 t, %1; cvt.u32.u64 %0, t; }"
        : "=r"(a) : "l"(p));
    return a;
}

__device__ __forceinline__ uint32_t bf2pack(float a, float b) {
    __nv_bfloat162 t;
    t.x = __float2bfloat16(a);
    t.y = __float2bfloat16(b);
    return *reinterpret_cast<uint32_t*>(&t);
}

__device__ __forceinline__ void mma16816(float* c, const uint32_t* a, const uint32_t* b) {
    asm volatile(
        "mma.sync.aligned.m16n8k16.row.col.f32.bf16.bf16.f32 "
        "{%0,%1,%2,%3}, {%4,%5,%6,%7}, {%8,%9}, {%0,%1,%2,%3};"
        : "+f"(c[0]), "+f"(c[1]), "+f"(c[2]), "+f"(c[3])
        : "r"(a[0]), "r"(a[1]), "r"(a[2]), "r"(a[3]), "r"(b[0]), "r"(b[1]));
}

__device__ __forceinline__ void ldsm4(uint32_t* r, uint32_t addr) {
    asm volatile("ldmatrix.sync.aligned.m8n8.x4.shared.b16 {%0,%1,%2,%3}, [%4];"
        : "=r"(r[0]), "=r"(r[1]), "=r"(r[2]), "=r"(r[3]) : "r"(addr));
}

__device__ __forceinline__ void cpa16(uint32_t sa, const void* g) {
    asm volatile("cp.async.cg.shared.global [%0], [%1], 16;" :: "r"(sa), "l"(g));
}
#define CP_COMMIT() asm volatile("cp.async.commit_group;" ::: "memory")
#define CP_WAIT0()  asm volatile("cp.async.wait_group 0;" ::: "memory")

// ---------------- weight prep: W[K,256] -> Wt[256,KP] hi/lo, zero-padded ----
__global__ void wprep_kernel(const float* __restrict__ W,
                             __nv_bfloat16* __restrict__ th,
                             __nv_bfloat16* __restrict__ tl, int K, int KP)
{
    int i = blockIdx.x * 256 + threadIdx.x;
    if (i >= 256 * KP) return;
    int n = i / KP, k = i % KP;
    float v = (k < K) ? __ldg(&W[k * 256 + n]) : 0.f;
    __nv_bfloat16 h = __float2bfloat16(v);
    float lo = v - __bfloat162float(h);
    th[i] = h;
    tl[i] = __float2bfloat16(lo);
}

// ---------------- mma.sync GEMM: C[M,256] = A[M,K] @ Wt^T (+bias) ----------
// CTA tile 128x256, 256 threads (8 warps, warp tile 64x64). 3-pass hi/lo split.
#define KROWB 80
#define OFF_AH 0
#define OFF_AL 10240
#define OFF_BH 20480
#define OFF_BL 40960
#define BUFSZ  61440
#define MM_SMEM (2 * BUFSZ)   /* 122880 */

__global__ void __launch_bounds__(256, 1)
mm_mma_kernel(const float* __restrict__ A,
              const __nv_bfloat16* __restrict__ Bh,
              const __nv_bfloat16* __restrict__ Bl,
              const float* __restrict__ bias,
              float* __restrict__ C, int M, int Kdim, int KP)
{
    extern __shared__ char smem[];
    const uint32_t sb = smem_to_u32(smem);
    const int tid = threadIdx.x, wid = tid >> 5, lane = tid & 31;
    const int rg = wid >> 2, cg = wid & 3;           // 2 row-groups x 4 col-groups
    const int r0 = blockIdx.x * 128;

    float acc[4][8][4];
#pragma unroll
    for (int mt = 0; mt < 4; mt++)
#pragma unroll
        for (int nt = 0; nt < 8; nt++)
#pragma unroll
            for (int j = 0; j < 4; j++) acc[mt][nt][j] = 0.f;

    const int NCH = KP >> 5;
    const int arow = tid >> 1;
    const int acol0 = (tid & 1) * 16;
    const bool arok = (r0 + arow) < M;
    const float* Abase = A + (size_t)(r0 + arow) * Kdim;

    float apf[16];

#define LDG_CHUNK(K0) do {                                                   \
    _Pragma("unroll")                                                        \
    for (int ii = 0; ii < 4; ii++) {                                         \
        int c = (K0) + acol0 + ii * 4;                                       \
        float4 v = make_float4(0.f, 0.f, 0.f, 0.f);                          \
        if (arok) {                                                          \
            if (c + 3 < Kdim) v = *(const float4*)(Abase + c);               \
            else {                                                           \
                if (c     < Kdim) v.x = Abase[c];                            \
                if (c + 1 < Kdim) v.y = Abase[c + 1];                        \
                if (c + 2 < Kdim) v.z = Abase[c + 2];                        \
                if (c + 3 < Kdim) v.w = Abase[c + 3];                        \
            }                                                                \
        }                                                                    \
        apf[ii*4+0] = v.x; apf[ii*4+1] = v.y;                                \
        apf[ii*4+2] = v.z; apf[ii*4+3] = v.w;                                \
    }                                                                        \
} while (0)

#define CPA_B(K0, BO) do {                                                   \
    uint32_t sh = sb + (BO) + OFF_BH + tid * KROWB;                          \
    uint32_t sl = sb + (BO) + OFF_BL + tid * KROWB;                          \
    const __nv_bfloat16* gh = Bh + (size_t)tid * KP + (K0);                  \
    const __nv_bfloat16* gl = Bl + (size_t)tid * KP + (K0);                  \
    _Pragma("unroll")                                                        \
    for (int q = 0; q < 4; q++) {                                            \
        cpa16(sh + q * 16, gh + q * 8);                                      \
        cpa16(sl + q * 16, gl + q * 8);                                      \
    }                                                                        \
    CP_COMMIT();                                                             \
} while (0)

    LDG_CHUNK(0);
    CPA_B(0, 0);

    // per-lane ldmatrix base offsets
    const uint32_t a_lm = (uint32_t)(rg * 64 + (lane & 15)) * KROWB + (lane >> 4) * 16;
    const int bmat = lane >> 3, brow = lane & 7;
    const uint32_t b_lm = (uint32_t)(cg * 64 + (bmat & 1) * 8 + brow) * KROWB + (bmat >> 1) * 16;

    for (int i = 0; i < NCH; i++) {
        const uint32_t bo = (uint32_t)(i & 1) * BUFSZ;

        // ---- STS A(i): fp32 -> bf16 hi/lo ----
        {
            uint32_t ph[8], pl[8];
#pragma unroll
            for (int j = 0; j < 8; j++) {
                float vx = apf[2 * j], vy = apf[2 * j + 1];
                float hx = __bfloat162float(__float2bfloat16(vx));
                float hy = __bfloat162float(__float2bfloat16(vy));
                ph[j] = bf2pack(vx, vy);
                pl[j] = bf2pack(vx - hx, vy - hy);
            }
            char* ab = smem + bo + arow * KROWB + acol0 * 2;
            *(uint4*)(ab + OFF_AH)      = make_uint4(ph[0], ph[1], ph[2], ph[3]);
            *(uint4*)(ab + OFF_AH + 16) = make_uint4(ph[4], ph[5], ph[6], ph[7]);
            *(uint4*)(ab + OFF_AL)      = make_uint4(pl[0], pl[1], pl[2], pl[3]);
            *(uint4*)(ab + OFF_AL + 16) = make_uint4(pl[4], pl[5], pl[6], pl[7]);
        }
        CP_WAIT0();
        __syncthreads();

        if (i + 1 < NCH) {
            LDG_CHUNK((i + 1) << 5);
            CPA_B((i + 1) << 5, ((i + 1) & 1) * BUFSZ);
        }

        // ---- compute chunk i ----
#pragma unroll
        for (int ks = 0; ks < 2; ks++) {
            const uint32_t kb = ks * 32;
            uint32_t ah[4][4], bh[8][2], bx[8][2];
#pragma unroll
            for (int mt = 0; mt < 4; mt++)
                ldsm4(ah[mt], sb + bo + OFF_AH + a_lm + mt * 16 * KROWB + kb);
#pragma unroll
            for (int ntp = 0; ntp < 4; ntp++) {
                uint32_t r[4];
                ldsm4(r, sb + bo + OFF_BH + b_lm + ntp * 16 * KROWB + kb);
                bh[2*ntp][0] = r[0]; bh[2*ntp+1][0] = r[1];
                bh[2*ntp][1] = r[2]; bh[2*ntp+1][1] = r[3];
            }
#pragma unroll
            for (int mt = 0; mt < 4; mt++)
#pragma unroll
                for (int nt = 0; nt < 8; nt++)
                    mma16816(acc[mt][nt], ah[mt], bh[nt]);
#pragma unroll
            for (int ntp = 0; ntp < 4; ntp++) {
                uint32_t r[4];
                ldsm4(r, sb + bo + OFF_BL + b_lm + ntp * 16 * KROWB + kb);
                bx[2*ntp][0] = r[0]; bx[2*ntp+1][0] = r[1];
                bx[2*ntp][1] = r[2]; bx[2*ntp+1][1] = r[3];
            }
#pragma unroll
            for (int mt = 0; mt < 4; mt++)
#pragma unroll
                for (int nt = 0; nt < 8; nt++)
                    mma16816(acc[mt][nt], ah[mt], bx[nt]);
#pragma unroll
            for (int mt = 0; mt < 4; mt++)
                ldsm4(ah[mt], sb + bo + OFF_AL + a_lm + mt * 16 * KROWB + kb);
#pragma unroll
            for (int mt = 0; mt < 4; mt++)
#pragma unroll
                for (int nt = 0; nt < 8; nt++)
                    mma16816(acc[mt][nt], ah[mt], bh[nt]);
        }
    }

    // ---- epilogue ----
#pragma unroll
    for (int nt = 0; nt < 8; nt++) {
        int c = cg * 64 + nt * 8 + (lane & 3) * 2;
        float b0v = bias ? __ldg(bias + c) : 0.f;
        float b1v = bias ? __ldg(bias + c + 1) : 0.f;
#pragma unroll
        for (int mt = 0; mt < 4; mt++) {
            int r = r0 + rg * 64 + mt * 16 + (lane >> 2);
            if (r < M)
                *(float2*)(C + (size_t)r * 256 + c) =
                    make_float2(acc[mt][nt][0] + b0v, acc[mt][nt][1] + b1v);
            if (r + 8 < M)
                *(float2*)(C + (size_t)(r + 8) * 256 + c) =
                    make_float2(acc[mt][nt][2] + b0v, acc[mt][nt][3] + b1v);
        }
    }
#undef LDG_CHUNK
#undef CPA_B
}

// ---------------- CSR build ------------------------------------------------
__global__ void deg_init_kernel(int* deg) {
    int i = blockIdx.x * blockDim.x + threadIdx.x;
    if (i < NN) deg[i] = 1;
}
__global__ void deg_count_kernel(const int* __restrict__ ei, int* deg) {
    int i = blockIdx.x * blockDim.x + threadIdx.x;
    if (i < EE) atomicAdd(&deg[ei[EE + i]], 1);
}
__global__ void scan_kernel(const int* __restrict__ deg, int* off, int* pos) {
    __shared__ int sm[1024];
    const int t = threadIdx.x;
    const int base = t * 40;
    int v[40];
    int local = 0;
#pragma unroll
    for (int i = 0; i < 40; i++) {
        int idx = base + i;
        int d = (idx < NN) ? deg[idx] : 0;
        v[i] = local;
        local += d;
    }
    sm[t] = local;
    __syncthreads();
    for (int o = 1; o < 1024; o <<= 1) {
        int add = (t >= o) ? sm[t - o] : 0;
        __syncthreads();
        sm[t] += add;
        __syncthreads();
    }
    int excl = sm[t] - local;
#pragma unroll
    for (int i = 0; i < 40; i++) {
        int idx = base + i;
        if (idx < NN) {
            int o_ = excl + v[i];
            off[idx] = o_;
            pos[idx] = o_;
        }
    }
    if (t == 1023) off[NN] = sm[1023];
}
__global__ void csr_fill_kernel(const int* __restrict__ ei, int* pos, int* csr) {
    int i = blockIdx.x * blockDim.x + threadIdx.x;
    if (i >= ETOT) return;
    int s, d;
    if (i < EE) { s = ei[i]; d = ei[EE + i]; }
    else        { s = d = i - EE; }
    int p = atomicAdd(&pos[d], 1);
    csr[p] = s;
}

// ---------------- attention scores ----------------------------------------
template <int H, int C>
__global__ void scores_kernel(const float* __restrict__ h,
                              const float* __restrict__ asrc,
                              const float* __restrict__ adst,
                              float* __restrict__ ssrc, float* __restrict__ sdst)
{
    int gw = (blockIdx.x * blockDim.x + threadIdx.x) >> 5;
    if (gw >= NN) return;
    int lane = threadIdx.x & 31;

    const float4* hp = (const float4*)(h + gw * 256 + lane * 8);
    float4 v0 = hp[0], v1 = hp[1];
    const float4* ap = (const float4*)(asrc + lane * 8);
    float4 a0 = ap[0], a1 = ap[1];
    const float4* dp = (const float4*)(adst + lane * 8);
    float4 d0 = dp[0], d1 = dp[1];

    float ps = v0.x * a0.x + v0.y * a0.y + v0.z * a0.z + v0.w * a0.w +
               v1.x * a1.x + v1.y * a1.y + v1.z * a1.z + v1.w * a1.w;
    float pd = v0.x * d0.x + v0.y * d0.y + v0.z * d0.z + v0.w * d0.w +
               v1.x * d1.x + v1.y * d1.y + v1.z * d1.z + v1.w * d1.w;

    const int GC = C / 8;
#pragma unroll
    for (int o = 1; o < GC; o <<= 1) {
        ps += __shfl_xor_sync(0xffffffffu, ps, o);
        pd += __shfl_xor_sync(0xffffffffu, pd, o);
    }
    int myh = lane / GC;
    if ((lane & (GC - 1)) == 0) {
        ssrc[gw * H + myh] = ps;
        sdst[gw * H + myh] = pd;
    }
}

// ------- GAT aggregation fused with bias+elu+residual+LN (+ pooling) -------
template <int H, int C, bool POOL>
__global__ void agg_fused_kernel(const float* __restrict__ ssrc,
                                 const float* __restrict__ sdst,
                                 const float* __restrict__ h,
                                 const int* __restrict__ off,
                                 const int* __restrict__ csr,
                                 const float* __restrict__ bias,
                                 const float* __restrict__ xin,
                                 const float* __restrict__ g,
                                 const float* __restrict__ be,
                                 float* __restrict__ xout,
                                 const float* __restrict__ x0p,
                                 const int* __restrict__ batch,
                                 float* __restrict__ p2,
                                 float* __restrict__ p0,
                                 float* __restrict__ cnt)
{
    int gw = (blockIdx.x * blockDim.x + threadIdx.x) >> 5;
    if (gw >= NN) return;
    int lane = threadIdx.x & 31;

    int e0 = off[gw];
    int deg = off[gw + 1] - e0;

    const int ES = 32 / H;
    int hh = lane % H;
    int j0 = lane / H;

    // passes 1+2 merged (online softmax)
    float sd = __ldg(&sdst[gw * H + hh]);
    float m = -1e30f, z = 0.f;
    for (int j = j0; j < deg; j += ES) {
        int s = __ldg(&csr[e0 + j]);
        float e = __ldg(&ssrc[s * H + hh]) + sd;
        e = e > 0.f ? e : 0.2f * e;
        float mn = fmaxf(m, e);
        z = z * __expf(m - mn) + __expf(e - mn);
        m = mn;
    }
#pragma unroll
    for (int o = H; o < 32; o <<= 1) {
        float mo = __shfl_xor_sync(0xffffffffu, m, o);
        float zo = __shfl_xor_sync(0xffffffffu, z, o);
        float mn = fmaxf(m, mo);
        z = z * __expf(m - mn) + zo * __expf(mo - mn);
        m = mn;
    }

    // pass 3: lane owns cols [lane*8, lane*8+8) -> exactly one head
    const int myh = (lane * 8) / C;
    float my_m  = __shfl_sync(0xffffffffu, m, myh);
    float my_zi = 1.f / __shfl_sync(0xffffffffu, z, myh);
    float my_sd = __ldg(&sdst[gw * H + myh]);

    float acc[8] = {0.f, 0.f, 0.f, 0.f, 0.f, 0.f, 0.f, 0.f};
    for (int j = 0; j < deg; j++) {
        int s = __ldg(&csr[e0 + j]);
        float e = __ldg(&ssrc[s * H + myh]) + my_sd;
        e = e > 0.f ? e : 0.2f * e;
        float a = __expf(e - my_m) * my_zi;
        const float4* hp = (const float4*)(h + s * 256 + lane * 8);
        float4 v0 = __ldg(hp);
        float4 v1 = __ldg(hp + 1);
        acc[0] += a * v0.x; acc[1] += a * v0.y; acc[2] += a * v0.z; acc[3] += a * v0.w;
        acc[4] += a * v1.x; acc[5] += a * v1.y; acc[6] += a * v1.z; acc[7] += a * v1.w;
    }

    // epilogue: bias + elu + residual + layernorm
    int base = gw * 256 + lane * 8;
    float4 b0 = *(const float4*)(bias + lane * 8);
    float4 b1 = *(const float4*)(bias + lane * 8 + 4);
    float4 x0v = *(const float4*)(xin + base);
    float4 x1v = *(const float4*)(xin + base + 4);
    float bb[8] = {b0.x, b0.y, b0.z, b0.w, b1.x, b1.y, b1.z, b1.w};
    float xv[8] = {x0v.x, x0v.y, x0v.z, x0v.w, x1v.x, x1v.y, x1v.z, x1v.w};

    float v[8];
    float sum = 0.f, sq = 0.f;
#pragma unroll
    for (int k = 0; k < 8; k++) {
        float t = acc[k] + bb[k];
        t = (t > 0.f) ? t : (__expf(t) - 1.f);   // elu
        t += xv[k];
        v[k] = t;
        sum += t;
        sq += t * t;
    }
#pragma unroll
    for (int o = 1; o < 32; o <<= 1) {
        sum += __shfl_xor_sync(0xffffffffu, sum, o);
        sq  += __shfl_xor_sync(0xffffffffu, sq, o);
    }
    float mean = sum * (1.f / 256.f);
    float var  = sq * (1.f / 256.f) - mean * mean;
    float rs   = rsqrtf(var + 1e-5f);

    float4 g0 = *(const float4*)(g + lane * 8);
    float4 g1 = *(const float4*)(g + lane * 8 + 4);
    float4 e0v = *(const float4*)(be + lane * 8);
    float4 e1v = *(const float4*)(be + lane * 8 + 4);
    float gv[8] = {g0.x, g0.y, g0.z, g0.w, g1.x, g1.y, g1.z, g1.w};
    float ev[8] = {e0v.x, e0v.y, e0v.z, e0v.w, e1v.x, e1v.y, e1v.z, e1v.w};

    float o0[8];
#pragma unroll
    for (int k = 0; k < 8; k++) o0[k] = (v[k] - mean) * rs * gv[k] + ev[k];

    if (!POOL) {
        *(float4*)(xout + base)     = make_float4(o0[0], o0[1], o0[2], o0[3]);
        *(float4*)(xout + base + 4) = make_float4(o0[4], o0[5], o0[6], o0[7]);
    } else {
        int b = __ldg(&batch[gw]);
        float* pp2 = p2 + b * 256 + lane * 8;
        float* pp0 = p0 + b * 256 + lane * 8;
        float4 z0 = *(const float4*)(x0p + base);
        float4 z1 = *(const float4*)(x0p + base + 4);
        float zv[8] = {z0.x, z0.y, z0.z, z0.w, z1.x, z1.y, z1.z, z1.w};
#pragma unroll
        for (int k = 0; k < 8; k++) {
            atomicAdd(pp2 + k, o0[k]);
            atomicAdd(pp0 + k, zv[k]);
        }
        if (lane == 0) atomicAdd(&cnt[b], 1.f);
    }
}

// ---------------- pooling init ---------------------------------------------
__global__ void pool_init_kernel(float* p2, float* p0, float* cnt) {
    int i = blockIdx.x * blockDim.x + threadIdx.x;
    if (i < BB * DD) { p2[i] = 0.f; p0[i] = 0.f; }
    if (i < BB) cnt[i] = 0.f;
}

// ---------------- classification head (block per graph) -------------------
__global__ void head_kernel(const float* __restrict__ p2,
                            const float* __restrict__ p0,
                            const float* __restrict__ cnt,
                            const float* __restrict__ Wf,  const float* __restrict__ bf,
                            const float* __restrict__ Wc1, const float* __restrict__ bc1,
                            const float* __restrict__ Wc2, const float* __restrict__ bc2,
                            float* __restrict__ out)
{
    __shared__ float xc[512];
    __shared__ float f[256];
    __shared__ float c1[128];
    __shared__ float lg[20];

    int b = blockIdx.x, t = threadIdx.x;
    float c = fmaxf(cnt[b], 1.f);
    xc[t]       = p2[b * 256 + t] / c;
    xc[256 + t] = p0[b * 256 + t] / c;
    __syncthreads();

    float acc = bf[t];
    for (int i = 0; i < 512; i++) acc += xc[i] * Wf[i * 256 + t];
    f[t] = fmaxf(acc, 0.f);
    __syncthreads();

    if (t < 128) {
        float a = bc1[t];
        for (int i = 0; i < 256; i++) a += f[i] * Wc1[i * 128 + t];
        c1[t] = fmaxf(a, 0.f);
    }
    __syncthreads();

    if (t < 20) {
        float a = bc2[t];
        for (int i = 0; i < 128; i++) a += c1[i] * Wc2[i * 20 + t];
        lg[t] = a;
    }
    __syncthreads();

    if (t < 32) {
        float v = (t < 20) ? lg[t] : -1e30f;
        float m = v;
#pragma unroll
        for (int o = 1; o < 32; o <<= 1) m = fmaxf(m, __shfl_xor_sync(0xffffffffu, m, o));
        float e = (t < 20) ? expf(v - m) : 0.f;
        float s = e;
#pragma unroll
        for (int o = 1; o < 32; o <<= 1) s += __shfl_xor_sync(0xffffffffu, s, o);
        if (t < 20) out[b * 20 + t] = v - m - logf(s);
    }
}

// ---------------- launcher -------------------------------------------------
extern "C" void kernel_launch(void* const* d_in, const int* in_sizes, int n_in,
                              void* d_out, int out_size)
{
    const float* x    = (const float*)d_in[0];
    const int*   ei   = (const int*)  d_in[1];
    const int*   batch= (const int*)  d_in[2];
    const float* W_in = (const float*)d_in[3];
    const float* b_in = (const float*)d_in[4];
    const float* W1   = (const float*)d_in[5];
    const float* as1  = (const float*)d_in[6];
    const float* ad1  = (const float*)d_in[7];
    const float* b1   = (const float*)d_in[8];
    const float* g1   = (const float*)d_in[9];
    const float* be1  = (const float*)d_in[10];
    const float* W2   = (const float*)d_in[11];
    const float* as2  = (const float*)d_in[12];
    const float* ad2  = (const float*)d_in[13];
    const float* b2   = (const float*)d_in[14];
    const float* g2   = (const float*)d_in[15];
    const float* be2  = (const float*)d_in[16];
    const float* Wf   = (const float*)d_in[17];
    const float* bfv  = (const float*)d_in[18];
    const float* Wc1  = (const float*)d_in[19];
    const float* bc1  = (const float*)d_in[20];
    const float* Wc2  = (const float*)d_in[21];
    const float* bc2  = (const float*)d_in[22];
    float* out = (float*)d_out;

    float *x0, *x1, *h, *ssrc, *sdst, *p2, *p0, *cnt;
    int *deg, *off, *pos, *csr;
    __nv_bfloat16 *wbh, *wbl, *w1h, *w1l, *w2h, *w2l;
    cudaGetSymbolAddress((void**)&x0,  g_x0);
    cudaGetSymbolAddress((void**)&x1,  g_x1);
    cudaGetSymbolAddress((void**)&h,   g_h);
    cudaGetSymbolAddress((void**)&ssrc,g_ssrc);
    cudaGetSymbolAddress((void**)&sdst,g_sdst);
    cudaGetSymbolAddress((void**)&deg, g_deg);
    cudaGetSymbolAddress((void**)&off, g_off);
    cudaGetSymbolAddress((void**)&pos, g_pos);
    cudaGetSymbolAddress((void**)&csr, g_csr);
    cudaGetSymbolAddress((void**)&p2,  g_p2);
    cudaGetSymbolAddress((void**)&p0,  g_p0);
    cudaGetSymbolAddress((void**)&cnt, g_cnt);
    cudaGetSymbolAddress((void**)&wbh, g_wbt_hi);
    cudaGetSymbolAddress((void**)&wbl, g_wbt_lo);
    cudaGetSymbolAddress((void**)&w1h, g_w1t_hi);
    cudaGetSymbolAddress((void**)&w1l, g_w1t_lo);
    cudaGetSymbolAddress((void**)&w2h, g_w2t_hi);
    cudaGetSymbolAddress((void**)&w2l, g_w2t_lo);

    cudaFuncSetAttribute(mm_mma_kernel, cudaFuncAttributeMaxDynamicSharedMemorySize, MM_SMEM);

    const int WARP_BLOCKS = NN / 8;
    const int MMGRID = (NN + 127) / 128;   // 313

    // 0: big weight prep
    wprep_kernel<<<(256 * KPBIG + 255) / 256, 256>>>(W_in, wbh, wbl, KBIG, KPBIG);
    // 1-4: CSR build
    deg_init_kernel<<<(NN + 255) / 256, 256>>>(deg);
    deg_count_kernel<<<(EE + 255) / 256, 256>>>(ei, deg);
    scan_kernel<<<1, 1024>>>(deg, off, pos);
    csr_fill_kernel<<<(ETOT + 255) / 256, 256>>>(ei, pos, csr);
    // 5: input projection  <- ncu -s 5 profiles this
    mm_mma_kernel<<<MMGRID, 256, MM_SMEM>>>(x, wbh, wbl, b_in, x0, NN, KBIG, KPBIG);
    // 6-7: conv weight preps
    wprep_kernel<<<(256 * 256 + 255) / 256, 256>>>(W1, w1h, w1l, 256, 256);
    wprep_kernel<<<(256 * 256 + 255) / 256, 256>>>(W2, w2h, w2l, 256, 256);

    // conv1
    mm_mma_kernel<<<MMGRID, 256, MM_SMEM>>>(x0, w1h, w1l, nullptr, h, NN, 256, 256);
    scores_kernel<8, 32><<<WARP_BLOCKS, 256>>>(h, as1, ad1, ssrc, sdst);
    agg_fused_kernel<8, 32, false><<<WARP_BLOCKS, 256>>>(
        ssrc, sdst, h, off, csr, b1, x0, g1, be1, x1,
        nullptr, nullptr, nullptr, nullptr, nullptr);

    // conv2 (+ fused pooling)
    mm_mma_kernel<<<MMGRID, 256, MM_SMEM>>>(x1, w2h, w2l, nullptr, h, NN, 256, 256);
    scores_kernel<4, 64><<<WARP_BLOCKS, 256>>>(h, as2, ad2, ssrc, sdst);
    pool_init_kernel<<<64, 256>>>(p2, p0, cnt);
    agg_fused_kernel<4, 64, true><<<WARP_BLOCKS, 256>>>(
        ssrc, sdst, h, off, csr, b2, x1, g2, be2, nullptr,
        x0, batch, p2, p0, cnt);

    // head
    head_kernel<<<BB, 256>>>(p2, p0, cnt, Wf, bfv, Wc1, bc1, Wc2, bc2, out);
}

// round 6
// speedup vs baseline: 1.1465x; 1.1465x over previous
#include <cuda_runtime.h>
#include <cuda_bf16.h>
#include <math.h>
#include <cstdint>

#define NN 40000
#define EE 1280000
#define ETOT (EE + NN)
#define DD 256
#define BB 64
#define NCLS 20
#define KBIG 5000
#define KPBIG 5024   /* 157 * 32 */

// ---------------- scratch (static device allocations) ----------------------
__device__ float g_x0[NN * DD];
__device__ float g_x1[NN * DD];
__device__ float g_h[NN * DD];
__device__ float g_ssrc[NN * 8];
__device__ float g_sdst[NN * 8];
__device__ int   g_deg[NN];
__device__ int   g_off[NN + 1];
__device__ int   g_pos[NN];
__device__ int   g_csr[ETOT];
__device__ float g_p2[BB * DD];
__device__ float g_p0[BB * DD];
__device__ float g_cnt[BB];
__device__ __nv_bfloat16 g_wbt_hi[256 * KPBIG];
__device__ __nv_bfloat16 g_wbt_lo[256 * KPBIG];
__device__ __nv_bfloat16 g_w1t_hi[256 * 256];
__device__ __nv_bfloat16 g_w1t_lo[256 * 256];
__device__ __nv_bfloat16 g_w2t_hi[256 * 256];
__device__ __nv_bfloat16 g_w2t_lo[256 * 256];

__device__ __forceinline__ uint32_t bf2pack(float a, float b) {
    __nv_bfloat162 t;
    t.x = __float2bfloat16(a);
    t.y = __float2bfloat16(b);
    return *reinterpret_cast<uint32_t*>(&t);
}

__device__ __forceinline__ void mma16816(float* c, const uint32_t* a, const uint32_t* b) {
    asm volatile(
        "mma.sync.aligned.m16n8k16.row.col.f32.bf16.bf16.f32 "
        "{%0,%1,%2,%3}, {%4,%5,%6,%7}, {%8,%9}, {%0,%1,%2,%3};"
        : "+f"(c[0]), "+f"(c[1]), "+f"(c[2]), "+f"(c[3])
        : "r"(a[0]), "r"(a[1]), "r"(a[2]), "r"(a[3]), "r"(b[0]), "r"(b[1]));
}

// ---------------- weight prep: W[K,256] -> Wt[256,KP] hi/lo, zero-padded ----
__global__ void wprep_kernel(const float* __restrict__ W,
                             __nv_bfloat16* __restrict__ th,
                             __nv_bfloat16* __restrict__ tl, int K, int KP)
{
    int i = blockIdx.x * 256 + threadIdx.x;
    if (i >= 256 * KP) return;
    int n = i / KP, k = i % KP;
    float v = (k < K) ? __ldg(&W[k * 256 + n]) : 0.f;
    __nv_bfloat16 h = __float2bfloat16(v);
    float lo = v - __bfloat162float(h);
    th[i] = h;
    tl[i] = __float2bfloat16(lo);
}

// ---------------- mma.sync GEMM: C[M,256] = A[M,K] @ Wt^T (+bias) ----------
// Round-3 proven shape: CTA tile 128x128 (grid.y = col half), 8 warps,
// warp tile 64x32 -> 64 accs/thread, no spills.
#define KROWB 80                     /* bytes per smem row (32 halves + pad) */
#define ABUF_H 0
#define ABUF_L (128 * KROWB)         /* 10240 */
#define BBUF_H (2 * 128 * KROWB)     /* 20480 */
#define BBUF_L (3 * 128 * KROWB)     /* 30720 */
#define BUFSZ  (4 * 128 * KROWB)     /* 40960 */
#define MM_SMEM (2 * BUFSZ)          /* 81920 */

__global__ void __launch_bounds__(256, 1)
mm_mma_kernel(const float* __restrict__ A,
              const __nv_bfloat16* __restrict__ Bh,
              const __nv_bfloat16* __restrict__ Bl,
              const float* __restrict__ bias,
              float* __restrict__ C, int M, int Kdim, int KP)
{
    extern __shared__ char smem[];
    const int tid = threadIdx.x, wid = tid >> 5, lane = tid & 31;
    const int group = lane >> 2, tig = lane & 3;
    const int rg = wid >> 2, cg = wid & 3;
    const int r0 = blockIdx.x * 128, n0 = blockIdx.y * 128;

    float acc[4][4][4];
#pragma unroll
    for (int mt = 0; mt < 4; mt++)
#pragma unroll
        for (int nt = 0; nt < 4; nt++)
#pragma unroll
            for (int j = 0; j < 4; j++) acc[mt][nt][j] = 0.f;

    const int NCH = KP >> 5;
    const int arow = tid >> 1;
    const int acol0 = (tid & 1) * 16;
    const bool arok = (r0 + arow) < M;
    const float* Abase = A + (size_t)(r0 + arow) * Kdim;

    float apf[16];
    uint4 bpfh[2], bpfl[2];

#define LDG_CHUNK(K0) do {                                                   \
    _Pragma("unroll")                                                        \
    for (int ii = 0; ii < 4; ii++) {                                         \
        int c = (K0) + acol0 + ii * 4;                                       \
        float4 v = make_float4(0.f, 0.f, 0.f, 0.f);                          \
        if (arok) {                                                          \
            if (c + 3 < Kdim) v = *(const float4*)(Abase + c);               \
            else {                                                           \
                if (c     < Kdim) v.x = Abase[c];                            \
                if (c + 1 < Kdim) v.y = Abase[c + 1];                        \
                if (c + 2 < Kdim) v.z = Abase[c + 2];                        \
                if (c + 3 < Kdim) v.w = Abase[c + 3];                        \
            }                                                                \
        }                                                                    \
        apf[ii*4+0] = v.x; apf[ii*4+1] = v.y;                                \
        apf[ii*4+2] = v.z; apf[ii*4+3] = v.w;                                \
    }                                                                        \
    _Pragma("unroll")                                                        \
    for (int q = 0; q < 2; q++) {                                            \
        int idx = tid * 2 + q;                                               \
        int n = idx >> 2, seg = idx & 3;                                     \
        size_t so = (size_t)(n0 + n) * KP + (K0) + seg * 8;                  \
        bpfh[q] = *(const uint4*)(Bh + so);                                  \
        bpfl[q] = *(const uint4*)(Bl + so);                                  \
    }                                                                        \
} while (0)

    LDG_CHUNK(0);

    for (int i = 0; i < NCH; i++) {
        char* buf = smem + (size_t)(i & 1) * BUFSZ;

        // ---- STS (convert A fp32 -> bf16 hi/lo) ----
        {
            uint32_t ph[8], pl[8];
#pragma unroll
            for (int j = 0; j < 8; j++) {
                float vx = apf[2 * j], vy = apf[2 * j + 1];
                float hx = __bfloat162float(__float2bfloat16(vx));
                float hy = __bfloat162float(__float2bfloat16(vy));
                ph[j] = bf2pack(vx, vy);
                pl[j] = bf2pack(vx - hx, vy - hy);
            }
            uint32_t aoff = arow * KROWB + acol0 * 2;
            *(uint4*)(buf + ABUF_H + aoff)      = make_uint4(ph[0], ph[1], ph[2], ph[3]);
            *(uint4*)(buf + ABUF_H + aoff + 16) = make_uint4(ph[4], ph[5], ph[6], ph[7]);
            *(uint4*)(buf + ABUF_L + aoff)      = make_uint4(pl[0], pl[1], pl[2], pl[3]);
            *(uint4*)(buf + ABUF_L + aoff + 16) = make_uint4(pl[4], pl[5], pl[6], pl[7]);
#pragma unroll
            for (int q = 0; q < 2; q++) {
                int idx = tid * 2 + q;
                int n = idx >> 2, seg = idx & 3;
                uint32_t boff = n * KROWB + seg * 16;
                *(uint4*)(buf + BBUF_H + boff) = bpfh[q];
                *(uint4*)(buf + BBUF_L + boff) = bpfl[q];
            }
        }
        __syncthreads();

        if (i + 1 < NCH) LDG_CHUNK((i + 1) << 5);

        // ---- compute: 2 k-steps x (hh, hl, lh) ----
#pragma unroll
        for (int ks = 0; ks < 2; ks++) {
            const uint32_t kb = (uint32_t)(ks * 16 + tig * 2) * 2;
            uint32_t ah[4][4], bhf[4][2], blf[4][2], alf[4][4];
#pragma unroll
            for (int mt = 0; mt < 4; mt++) {
                uint32_t rb = (uint32_t)(rg * 64 + mt * 16 + group) * KROWB;
                ah[mt][0] = *(const uint32_t*)(buf + ABUF_H + rb + kb);
                ah[mt][1] = *(const uint32_t*)(buf + ABUF_H + rb + 8 * KROWB + kb);
                ah[mt][2] = *(const uint32_t*)(buf + ABUF_H + rb + kb + 16);
                ah[mt][3] = *(const uint32_t*)(buf + ABUF_H + rb + 8 * KROWB + kb + 16);
            }
#pragma unroll
            for (int nt = 0; nt < 4; nt++) {
                uint32_t nb = (uint32_t)(cg * 32 + nt * 8 + group) * KROWB;
                bhf[nt][0] = *(const uint32_t*)(buf + BBUF_H + nb + kb);
                bhf[nt][1] = *(const uint32_t*)(buf + BBUF_H + nb + kb + 16);
            }
#pragma unroll
            for (int mt = 0; mt < 4; mt++)
#pragma unroll
                for (int nt = 0; nt < 4; nt++)
                    mma16816(acc[mt][nt], ah[mt], bhf[nt]);
#pragma unroll
            for (int nt = 0; nt < 4; nt++) {
                uint32_t nb = (uint32_t)(cg * 32 + nt * 8 + group) * KROWB;
                blf[nt][0] = *(const uint32_t*)(buf + BBUF_L + nb + kb);
                blf[nt][1] = *(const uint32_t*)(buf + BBUF_L + nb + kb + 16);
            }
#pragma unroll
            for (int mt = 0; mt < 4; mt++)
#pragma unroll
                for (int nt = 0; nt < 4; nt++)
                    mma16816(acc[mt][nt], ah[mt], blf[nt]);
#pragma unroll
            for (int mt = 0; mt < 4; mt++) {
                uint32_t rb = (uint32_t)(rg * 64 + mt * 16 + group) * KROWB;
                alf[mt][0] = *(const uint32_t*)(buf + ABUF_L + rb + kb);
                alf[mt][1] = *(const uint32_t*)(buf + ABUF_L + rb + 8 * KROWB + kb);
                alf[mt][2] = *(const uint32_t*)(buf + ABUF_L + rb + kb + 16);
                alf[mt][3] = *(const uint32_t*)(buf + ABUF_L + rb + 8 * KROWB + kb + 16);
            }
#pragma unroll
            for (int mt = 0; mt < 4; mt++)
#pragma unroll
                for (int nt = 0; nt < 4; nt++)
                    mma16816(acc[mt][nt], alf[mt], bhf[nt]);
        }
    }

    // ---- epilogue ----
#pragma unroll
    for (int nt = 0; nt < 4; nt++) {
        int c = n0 + cg * 32 + nt * 8 + tig * 2;
        float b0v = bias ? __ldg(bias + c) : 0.f;
        float b1v = bias ? __ldg(bias + c + 1) : 0.f;
#pragma unroll
        for (int mt = 0; mt < 4; mt++) {
            int r = r0 + rg * 64 + mt * 16 + group;
            if (r < M)
                *(float2*)(C + (size_t)r * 256 + c) =
                    make_float2(acc[mt][nt][0] + b0v, acc[mt][nt][1] + b1v);
            if (r + 8 < M)
                *(float2*)(C + (size_t)(r + 8) * 256 + c) =
                    make_float2(acc[mt][nt][2] + b0v, acc[mt][nt][3] + b1v);
        }
    }
#undef LDG_CHUNK
}

// ---------------- CSR build ------------------------------------------------
__global__ void deg_init_kernel(int* deg) {
    int i = blockIdx.x * blockDim.x + threadIdx.x;
    if (i < NN) deg[i] = 1;
}
__global__ void deg_count_kernel(const int* __restrict__ ei, int* deg) {
    int i = blockIdx.x * blockDim.x + threadIdx.x;
    if (i < EE) atomicAdd(&deg[ei[EE + i]], 1);
}
__global__ void scan_kernel(const int* __restrict__ deg, int* off, int* pos) {
    __shared__ int sm[1024];
    const int t = threadIdx.x;
    const int base = t * 40;
    int v[40];
    int local = 0;
#pragma unroll
    for (int i = 0; i < 40; i++) {
        int idx = base + i;
        int d = (idx < NN) ? deg[idx] : 0;
        v[i] = local;
        local += d;
    }
    sm[t] = local;
    __syncthreads();
    for (int o = 1; o < 1024; o <<= 1) {
        int add = (t >= o) ? sm[t - o] : 0;
        __syncthreads();
        sm[t] += add;
        __syncthreads();
    }
    int excl = sm[t] - local;
#pragma unroll
    for (int i = 0; i < 40; i++) {
        int idx = base + i;
        if (idx < NN) {
            int o_ = excl + v[i];
            off[idx] = o_;
            pos[idx] = o_;
        }
    }
    if (t == 1023) off[NN] = sm[1023];
}
__global__ void csr_fill_kernel(const int* __restrict__ ei, int* pos, int* csr) {
    int i = blockIdx.x * blockDim.x + threadIdx.x;
    if (i >= ETOT) return;
    int s, d;
    if (i < EE) { s = ei[i]; d = ei[EE + i]; }
    else        { s = d = i - EE; }
    int p = atomicAdd(&pos[d], 1);
    csr[p] = s;
}

// ---------------- attention scores ----------------------------------------
template <int H, int C>
__global__ void scores_kernel(const float* __restrict__ h,
                              const float* __restrict__ asrc,
                              const float* __restrict__ adst,
                              float* __restrict__ ssrc, float* __restrict__ sdst)
{
    int gw = (blockIdx.x * blockDim.x + threadIdx.x) >> 5;
    if (gw >= NN) return;
    int lane = threadIdx.x & 31;

    const float4* hp = (const float4*)(h + gw * 256 + lane * 8);
    float4 v0 = hp[0], v1 = hp[1];
    const float4* ap = (const float4*)(asrc + lane * 8);
    float4 a0 = ap[0], a1 = ap[1];
    const float4* dp = (const float4*)(adst + lane * 8);
    float4 d0 = dp[0], d1 = dp[1];

    float ps = v0.x * a0.x + v0.y * a0.y + v0.z * a0.z + v0.w * a0.w +
               v1.x * a1.x + v1.y * a1.y + v1.z * a1.z + v1.w * a1.w;
    float pd = v0.x * d0.x + v0.y * d0.y + v0.z * d0.z + v0.w * d0.w +
               v1.x * d1.x + v1.y * d1.y + v1.z * d1.z + v1.w * d1.w;

    const int GC = C / 8;
#pragma unroll
    for (int o = 1; o < GC; o <<= 1) {
        ps += __shfl_xor_sync(0xffffffffu, ps, o);
        pd += __shfl_xor_sync(0xffffffffu, pd, o);
    }
    int myh = lane / GC;
    if ((lane & (GC - 1)) == 0) {
        ssrc[gw * H + myh] = ps;
        sdst[gw * H + myh] = pd;
    }
}

// ------- GAT aggregation fused with bias+elu+residual+LN (+ pooling) -------
template <int H, int C, bool POOL>
__global__ void agg_fused_kernel(const float* __restrict__ ssrc,
                                 const float* __restrict__ sdst,
                                 const float* __restrict__ h,
                                 const int* __restrict__ off,
                                 const int* __restrict__ csr,
                                 const float* __restrict__ bias,
                                 const float* __restrict__ xin,
                                 const float* __restrict__ g,
                                 const float* __restrict__ be,
                                 float* __restrict__ xout,
                                 const float* __restrict__ x0p,
                                 const int* __restrict__ batch,
                                 float* __restrict__ p2,
                                 float* __restrict__ p0,
                                 float* __restrict__ cnt)
{
    int gw = (blockIdx.x * blockDim.x + threadIdx.x) >> 5;
    if (gw >= NN) return;
    int lane = threadIdx.x & 31;

    int e0 = off[gw];
    int deg = off[gw + 1] - e0;

    const int ES = 32 / H;
    int hh = lane % H;
    int j0 = lane / H;

    // passes 1+2 merged (online softmax)
    float sd = __ldg(&sdst[gw * H + hh]);
    float m = -1e30f, z = 0.f;
    for (int j = j0; j < deg; j += ES) {
        int s = __ldg(&csr[e0 + j]);
        float e = __ldg(&ssrc[s * H + hh]) + sd;
        e = e > 0.f ? e : 0.2f * e;
        float mn = fmaxf(m, e);
        z = z * __expf(m - mn) + __expf(e - mn);
        m = mn;
    }
#pragma unroll
    for (int o = H; o < 32; o <<= 1) {
        float mo = __shfl_xor_sync(0xffffffffu, m, o);
        float zo = __shfl_xor_sync(0xffffffffu, z, o);
        float mn = fmaxf(m, mo);
        z = z * __expf(m - mn) + zo * __expf(mo - mn);
        m = mn;
    }

    // pass 3: lane owns cols [lane*8, lane*8+8) -> exactly one head
    const int myh = (lane * 8) / C;
    float my_m  = __shfl_sync(0xffffffffu, m, myh);
    float my_zi = 1.f / __shfl_sync(0xffffffffu, z, myh);
    float my_sd = __ldg(&sdst[gw * H + myh]);

    float acc[8] = {0.f, 0.f, 0.f, 0.f, 0.f, 0.f, 0.f, 0.f};
    for (int j = 0; j < deg; j++) {
        int s = __ldg(&csr[e0 + j]);
        float e = __ldg(&ssrc[s * H + myh]) + my_sd;
        e = e > 0.f ? e : 0.2f * e;
        float a = __expf(e - my_m) * my_zi;
        const float4* hp = (const float4*)(h + s * 256 + lane * 8);
        float4 v0 = __ldg(hp);
        float4 v1 = __ldg(hp + 1);
        acc[0] += a * v0.x; acc[1] += a * v0.y; acc[2] += a * v0.z; acc[3] += a * v0.w;
        acc[4] += a * v1.x; acc[5] += a * v1.y; acc[6] += a * v1.z; acc[7] += a * v1.w;
    }

    // epilogue: bias + elu + residual + layernorm
    int base = gw * 256 + lane * 8;
    float4 b0 = *(const float4*)(bias + lane * 8);
    float4 b1 = *(const float4*)(bias + lane * 8 + 4);
    float4 x0v = *(const float4*)(xin + base);
    float4 x1v = *(const float4*)(xin + base + 4);
    float bb[8] = {b0.x, b0.y, b0.z, b0.w, b1.x, b1.y, b1.z, b1.w};
    float xv[8] = {x0v.x, x0v.y, x0v.z, x0v.w, x1v.x, x1v.y, x1v.z, x1v.w};

    float v[8];
    float sum = 0.f, sq = 0.f;
#pragma unroll
    for (int k = 0; k < 8; k++) {
        float t = acc[k] + bb[k];
        t = (t > 0.f) ? t : (__expf(t) - 1.f);   // elu
        t += xv[k];
        v[k] = t;
        sum += t;
        sq += t * t;
    }
#pragma unroll
    for (int o = 1; o < 32; o <<= 1) {
        sum += __shfl_xor_sync(0xffffffffu, sum, o);
        sq  += __shfl_xor_sync(0xffffffffu, sq, o);
    }
    float mean = sum * (1.f / 256.f);
    float var  = sq * (1.f / 256.f) - mean * mean;
    float rs   = rsqrtf(var + 1e-5f);

    float4 g0 = *(const float4*)(g + lane * 8);
    float4 g1 = *(const float4*)(g + lane * 8 + 4);
    float4 e0v = *(const float4*)(be + lane * 8);
    float4 e1v = *(const float4*)(be + lane * 8 + 4);
    float gv[8] = {g0.x, g0.y, g0.z, g0.w, g1.x, g1.y, g1.z, g1.w};
    float ev[8] = {e0v.x, e0v.y, e0v.z, e0v.w, e1v.x, e1v.y, e1v.z, e1v.w};

    float o0[8];
#pragma unroll
    for (int k = 0; k < 8; k++) o0[k] = (v[k] - mean) * rs * gv[k] + ev[k];

    if (!POOL) {
        *(float4*)(xout + base)     = make_float4(o0[0], o0[1], o0[2], o0[3]);
        *(float4*)(xout + base + 4) = make_float4(o0[4], o0[5], o0[6], o0[7]);
    } else {
        int b = __ldg(&batch[gw]);
        float* pp2 = p2 + b * 256 + lane * 8;
        float* pp0 = p0 + b * 256 + lane * 8;
        float4 z0 = *(const float4*)(x0p + base);
        float4 z1 = *(const float4*)(x0p + base + 4);
        float zv[8] = {z0.x, z0.y, z0.z, z0.w, z1.x, z1.y, z1.z, z1.w};
#pragma unroll
        for (int k = 0; k < 8; k++) {
            atomicAdd(pp2 + k, o0[k]);
            atomicAdd(pp0 + k, zv[k]);
        }
        if (lane == 0) atomicAdd(&cnt[b], 1.f);
    }
}

// ---------------- pooling init ---------------------------------------------
__global__ void pool_init_kernel(float* p2, float* p0, float* cnt) {
    int i = blockIdx.x * blockDim.x + threadIdx.x;
    if (i < BB * DD) { p2[i] = 0.f; p0[i] = 0.f; }
    if (i < BB) cnt[i] = 0.f;
}

// ---------------- classification head (block per graph) -------------------
__global__ void head_kernel(const float* __restrict__ p2,
                            const float* __restrict__ p0,
                            const float* __restrict__ cnt,
                            const float* __restrict__ Wf,  const float* __restrict__ bf,
                            const float* __restrict__ Wc1, const float* __restrict__ bc1,
                            const float* __restrict__ Wc2, const float* __restrict__ bc2,
                            float* __restrict__ out)
{
    __shared__ float xc[512];
    __shared__ float f[256];
    __shared__ float c1[128];
    __shared__ float lg[20];

    int b = blockIdx.x, t = threadIdx.x;
    float c = fmaxf(cnt[b], 1.f);
    xc[t]       = p2[b * 256 + t] / c;
    xc[256 + t] = p0[b * 256 + t] / c;
    __syncthreads();

    float acc = bf[t];
    for (int i = 0; i < 512; i++) acc += xc[i] * Wf[i * 256 + t];
    f[t] = fmaxf(acc, 0.f);
    __syncthreads();

    if (t < 128) {
        float a = bc1[t];
        for (int i = 0; i < 256; i++) a += f[i] * Wc1[i * 128 + t];
        c1[t] = fmaxf(a, 0.f);
    }
    __syncthreads();

    if (t < 20) {
        float a = bc2[t];
        for (int i = 0; i < 128; i++) a += c1[i] * Wc2[i * 20 + t];
        lg[t] = a;
    }
    __syncthreads();

    if (t < 32) {
        float v = (t < 20) ? lg[t] : -1e30f;
        float m = v;
#pragma unroll
        for (int o = 1; o < 32; o <<= 1) m = fmaxf(m, __shfl_xor_sync(0xffffffffu, m, o));
        float e = (t < 20) ? expf(v - m) : 0.f;
        float s = e;
#pragma unroll
        for (int o = 1; o < 32; o <<= 1) s += __shfl_xor_sync(0xffffffffu, s, o);
        if (t < 20) out[b * 20 + t] = v - m - logf(s);
    }
}

// ---------------- launcher -------------------------------------------------
extern "C" void kernel_launch(void* const* d_in, const int* in_sizes, int n_in,
                              void* d_out, int out_size)
{
    const float* x    = (const float*)d_in[0];
    const int*   ei   = (const int*)  d_in[1];
    const int*   batch= (const int*)  d_in[2];
    const float* W_in = (const float*)d_in[3];
    const float* b_in = (const float*)d_in[4];
    const float* W1   = (const float*)d_in[5];
    const float* as1  = (const float*)d_in[6];
    const float* ad1  = (const float*)d_in[7];
    const float* b1   = (const float*)d_in[8];
    const float* g1   = (const float*)d_in[9];
    const float* be1  = (const float*)d_in[10];
    const float* W2   = (const float*)d_in[11];
    const float* as2  = (const float*)d_in[12];
    const float* ad2  = (const float*)d_in[13];
    const float* b2   = (const float*)d_in[14];
    const float* g2   = (const float*)d_in[15];
    const float* be2  = (const float*)d_in[16];
    const float* Wf   = (const float*)d_in[17];
    const float* bfv  = (const float*)d_in[18];
    const float* Wc1  = (const float*)d_in[19];
    const float* bc1  = (const float*)d_in[20];
    const float* Wc2  = (const float*)d_in[21];
    const float* bc2  = (const float*)d_in[22];
    float* out = (float*)d_out;

    float *x0, *x1, *h, *ssrc, *sdst, *p2, *p0, *cnt;
    int *deg, *off, *pos, *csr;
    __nv_bfloat16 *wbh, *wbl, *w1h, *w1l, *w2h, *w2l;
    cudaGetSymbolAddress((void**)&x0,  g_x0);
    cudaGetSymbolAddress((void**)&x1,  g_x1);
    cudaGetSymbolAddress((void**)&h,   g_h);
    cudaGetSymbolAddress((void**)&ssrc,g_ssrc);
    cudaGetSymbolAddress((void**)&sdst,g_sdst);
    cudaGetSymbolAddress((void**)&deg, g_deg);
    cudaGetSymbolAddress((void**)&off, g_off);
    cudaGetSymbolAddress((void**)&pos, g_pos);
    cudaGetSymbolAddress((void**)&csr, g_csr);
    cudaGetSymbolAddress((void**)&p2,  g_p2);
    cudaGetSymbolAddress((void**)&p0,  g_p0);
    cudaGetSymbolAddress((void**)&cnt, g_cnt);
    cudaGetSymbolAddress((void**)&wbh, g_wbt_hi);
    cudaGetSymbolAddress((void**)&wbl, g_wbt_lo);
    cudaGetSymbolAddress((void**)&w1h, g_w1t_hi);
    cudaGetSymbolAddress((void**)&w1l, g_w1t_lo);
    cudaGetSymbolAddress((void**)&w2h, g_w2t_hi);
    cudaGetSymbolAddress((void**)&w2l, g_w2t_lo);

    cudaFuncSetAttribute(mm_mma_kernel, cudaFuncAttributeMaxDynamicSharedMemorySize, MM_SMEM);

    const int WARP_BLOCKS = NN / 8;
    const dim3 MMGRID((NN + 127) / 128, 2);   // 313 x 2

    // 0: big weight prep
    wprep_kernel<<<(256 * KPBIG + 255) / 256, 256>>>(W_in, wbh, wbl, KBIG, KPBIG);
    // 1-4: CSR build
    deg_init_kernel<<<(NN + 255) / 256, 256>>>(deg);
    deg_count_kernel<<<(EE + 255) / 256, 256>>>(ei, deg);
    scan_kernel<<<1, 1024>>>(deg, off, pos);
    csr_fill_kernel<<<(ETOT + 255) / 256, 256>>>(ei, pos, csr);
    // 5: input projection  <- ncu -s 5 profiles this
    mm_mma_kernel<<<MMGRID, 256, MM_SMEM>>>(x, wbh, wbl, b_in, x0, NN, KBIG, KPBIG);
    // conv weight preps
    wprep_kernel<<<(256 * 256 + 255) / 256, 256>>>(W1, w1h, w1l, 256, 256);
    wprep_kernel<<<(256 * 256 + 255) / 256, 256>>>(W2, w2h, w2l, 256, 256);

    // conv1
    mm_mma_kernel<<<MMGRID, 256, MM_SMEM>>>(x0, w1h, w1l, nullptr, h, NN, 256, 256);
    scores_kernel<8, 32><<<WARP_BLOCKS, 256>>>(h, as1, ad1, ssrc, sdst);
    agg_fused_kernel<8, 32, false><<<WARP_BLOCKS, 256>>>(
        ssrc, sdst, h, off, csr, b1, x0, g1, be1, x1,
        nullptr, nullptr, nullptr, nullptr, nullptr);

    // conv2 (+ fused pooling)
    mm_mma_kernel<<<MMGRID, 256, MM_SMEM>>>(x1, w2h, w2l, nullptr, h, NN, 256, 256);
    scores_kernel<4, 64><<<WARP_BLOCKS, 256>>>(h, as2, ad2, ssrc, sdst);
    pool_init_kernel<<<64, 256>>>(p2, p0, cnt);
    agg_fused_kernel<4, 64, true><<<WARP_BLOCKS, 256>>>(
        ssrc, sdst, h, off, csr, b2, x1, g2, be2, nullptr,
        x0, batch, p2, p0, cnt);

    // head
    head_kernel<<<BB, 256>>>(p2, p0, cnt, Wf, bfv, Wc1, bc1, Wc2, bc2, out);
}